// round 2
// baseline (speedup 1.0000x reference)
#include <cuda_runtime.h>
#include <cuda_fp16.h>
#include <cstdint>
#include <math.h>

// Problem constants
#define TOKENS 8192          // B*S
#define DDIM   1024
#define HDIM   4096
#define NEXP   8
#define TOTROWS (2*TOKENS)   // top-2 -> exactly 2*T expert-rows total

// ------------------------- device scratch (static, no allocs) ---------------
__device__ __half g_x16[(size_t)TOKENS * DDIM];                 // x in fp16
__device__ __half g_h[(size_t)(TOTROWS + 128) * HDIM];          // relu(xW1+b1), expert-sorted rows (+pad rows)
__device__ float  g_y[(size_t)TOTROWS * DDIM];                  // hW2+b2 per expert-row
__device__ int    g_cnt[NEXP];
__device__ int    g_off[NEXP];
__device__ int    g_idx[NEXP][TOKENS];                          // token id per expert slot
__device__ int    g_tok_e[TOKENS][2];
__device__ int    g_tok_p[TOKENS][2];
__device__ float  g_tok_g[TOKENS][2];

// ------------------------- small helpers ------------------------------------
__device__ __forceinline__ uint32_t s2u(const void* p) {
    return (uint32_t)__cvta_generic_to_shared(p);
}
__device__ __forceinline__ void ldsm_x4(uint32_t* r, uint32_t addr) {
    asm volatile("ldmatrix.sync.aligned.m8n8.x4.shared.b16 {%0,%1,%2,%3}, [%4];"
                 : "=r"(r[0]), "=r"(r[1]), "=r"(r[2]), "=r"(r[3]) : "r"(addr));
}
__device__ __forceinline__ void ldsm_x2t(uint32_t* r, uint32_t addr) {
    asm volatile("ldmatrix.sync.aligned.m8n8.x2.trans.shared.b16 {%0,%1}, [%2];"
                 : "=r"(r[0]), "=r"(r[1]) : "r"(addr));
}
__device__ __forceinline__ void mma16816(float* c, const uint32_t* a, const uint32_t* b) {
    asm volatile("mma.sync.aligned.m16n8k16.row.col.f32.f16.f16.f32 "
                 "{%0,%1,%2,%3}, {%4,%5,%6,%7}, {%8,%9}, {%0,%1,%2,%3};"
                 : "+f"(c[0]), "+f"(c[1]), "+f"(c[2]), "+f"(c[3])
                 : "r"(a[0]), "r"(a[1]), "r"(a[2]), "r"(a[3]), "r"(b[0]), "r"(b[1]));
}

// ------------------------- kernel 0: init -----------------------------------
__global__ void k_init() {
    if (threadIdx.x < NEXP) g_cnt[threadIdx.x] = 0;
}

// ------------------------- kernel 1: router ----------------------------------
// 1 warp per token: logits = x@Wr + br (fp32), softmax-top2 renormalized gates,
// atomic slot assignment per expert; also converts x row to fp16.
__global__ void k_router(const float* __restrict__ x,
                         const float* __restrict__ Wr,
                         const float* __restrict__ br) {
    int t    = blockIdx.x * 8 + (threadIdx.x >> 5);
    int lane = threadIdx.x & 31;
    if (t >= TOKENS) return;

    const float* xr = x + (size_t)t * DDIM;
    float acc[NEXP];
#pragma unroll
    for (int e = 0; e < NEXP; e++) acc[e] = 0.f;

    for (int j = 0; j < DDIM / 32; j++) {
        int d = j * 32 + lane;
        float xv = xr[d];
        g_x16[(size_t)t * DDIM + d] = __float2half_rn(xv);
        const float4* wr4 = (const float4*)(Wr + (size_t)d * NEXP);
        float4 w0 = wr4[0], w1 = wr4[1];
        acc[0] += xv * w0.x; acc[1] += xv * w0.y;
        acc[2] += xv * w0.z; acc[3] += xv * w0.w;
        acc[4] += xv * w1.x; acc[5] += xv * w1.y;
        acc[6] += xv * w1.z; acc[7] += xv * w1.w;
    }
#pragma unroll
    for (int o = 16; o; o >>= 1) {
#pragma unroll
        for (int e = 0; e < NEXP; e++)
            acc[e] += __shfl_xor_sync(0xffffffffu, acc[e], o);
    }

    if (lane == 0) {
#pragma unroll
        for (int e = 0; e < NEXP; e++) acc[e] += br[e];
        // top-1 (first max on tie, matching lax.top_k)
        int i0 = 0;
#pragma unroll
        for (int e = 1; e < NEXP; e++) if (acc[e] > acc[i0]) i0 = e;
        // top-2
        int i1 = -1;
#pragma unroll
        for (int e = 0; e < NEXP; e++) {
            if (e == i0) continue;
            if (i1 < 0 || acc[e] > acc[i1]) i1 = e;
        }
        // normalized top-2 softmax weights: full-softmax denominator cancels
        float ex = expf(acc[i1] - acc[i0]);
        float g0 = 1.f / (1.f + ex);
        float g1 = ex * g0;

        int p0 = atomicAdd(&g_cnt[i0], 1);
        int p1 = atomicAdd(&g_cnt[i1], 1);
        g_idx[i0][p0] = t;
        g_idx[i1][p1] = t;
        g_tok_e[t][0] = i0; g_tok_p[t][0] = p0; g_tok_g[t][0] = g0;
        g_tok_e[t][1] = i1; g_tok_p[t][1] = p1; g_tok_g[t][1] = g1;
    }
}

// ------------------------- kernel 2: offsets ---------------------------------
__global__ void k_offsets() {
    if (threadIdx.x == 0) {
        int s = 0;
        for (int e = 0; e < NEXP; e++) { g_off[e] = s; s += g_cnt[e]; }
    }
}

// ------------------------- kernel 3/4: grouped GEMM ---------------------------
// MODE 0: h[off+m, :] = relu( x16[gather(m), :KDIM] @ W1[e] + b1[e] )  (fp16 out)
// MODE 1: y[off+m, :] =        h[off+m, :KDIM]       @ W2[e] + b2[e]  (fp32 out)
// Tile 128x128x32, 256 threads, 8 warps as 2(m) x 4(n), warp tile 64x32.
#define BM 128
#define BN 128
#define BK 32
#define APAD 48    // halves per A-smem row (96B, 16B-aligned, reduces conflicts)
#define BPAD 136   // halves per B-smem row (272B, 16B-aligned)

template <int KDIM, int NDIM, int MODE>
__global__ __launch_bounds__(256) void k_gemm(const float* __restrict__ Wg,
                                              const float* __restrict__ biasg) {
    __shared__ __align__(16) __half As[2][BM * APAD];
    __shared__ __align__(16) __half Bs[2][BK * BPAD];

    const int e   = blockIdx.z;
    const int cnt = g_cnt[e];
    const int m0  = blockIdx.y * BM;
    if (m0 >= cnt) return;
    const int n0  = blockIdx.x * BN;
    const int off = g_off[e];
    const float* Wb = Wg + (size_t)e * KDIM * NDIM;

    const int tid  = threadIdx.x;
    const int lane = tid & 31;
    const int warp = tid >> 5;
    const int wm   = warp >> 2;   // 0..1
    const int wn   = warp & 3;    // 0..3

    // ---- A-load mapping: 2 x uint4 (8 halves) per thread, 128 rows x 4 segs
    const __half* aptr[2];
    int asoff[2];
#pragma unroll
    for (int l = 0; l < 2; l++) {
        int flat = tid + 256 * l;
        int row  = flat >> 2;       // 0..127
        int seg  = flat & 3;        // 0..3 (8-half segments)
        const __half* base;
        if (MODE == 0) {
            int tok = (m0 + row < cnt) ? g_idx[e][m0 + row] : 0;
            base = g_x16 + (size_t)tok * DDIM;
        } else {
            int rg = off + m0 + row;          // < TOTROWS+128 (padded)
            base = g_h + (size_t)rg * HDIM;
        }
        aptr[l]  = base + seg * 8;
        asoff[l] = row * APAD + seg * 8;
    }

    // ---- B-load mapping: 4 x float4 per thread, 32 rows x 32 float4-cols
    const float* bptr[4];
    int bsoff[4];
#pragma unroll
    for (int j = 0; j < 4; j++) {
        int idx = tid + 256 * j;    // 0..1023
        int row = idx >> 5;         // 0..31
        int col = (idx & 31) * 4;   // 0..124
        bptr[j]  = Wb + (size_t)row * NDIM + n0 + col;
        bsoff[j] = row * BPAD + col;
    }

    float acc[4][4][4];
#pragma unroll
    for (int mi = 0; mi < 4; mi++)
#pragma unroll
        for (int ni = 0; ni < 4; ni++)
#pragma unroll
            for (int q = 0; q < 4; q++) acc[mi][ni][q] = 0.f;

    uint4  ra[2];
    float4 rb[4];

    // prologue: chunk 0 -> smem[0]
#pragma unroll
    for (int l = 0; l < 2; l++) ra[l] = *(const uint4*)(aptr[l]);
#pragma unroll
    for (int j = 0; j < 4; j++) rb[j] = *(const float4*)(bptr[j]);
#pragma unroll
    for (int l = 0; l < 2; l++) *(uint4*)&As[0][asoff[l]] = ra[l];
#pragma unroll
    for (int j = 0; j < 4; j++) {
        __half2 h01 = __floats2half2_rn(rb[j].x, rb[j].y);
        __half2 h23 = __floats2half2_rn(rb[j].z, rb[j].w);
        uint2 pk = make_uint2(*(uint32_t*)&h01, *(uint32_t*)&h23);
        *(uint2*)&Bs[0][bsoff[j]] = pk;
    }
    __syncthreads();

    const int NK = KDIM / BK;
    for (int kc = 0; kc < NK; kc++) {
        const int buf = kc & 1;
        if (kc + 1 < NK) {
            int k0 = (kc + 1) * BK;
#pragma unroll
            for (int l = 0; l < 2; l++) ra[l] = *(const uint4*)(aptr[l] + k0);
#pragma unroll
            for (int j = 0; j < 4; j++) rb[j] = *(const float4*)(bptr[j] + (size_t)k0 * NDIM);
        }

        // compute from smem[buf]
#pragma unroll
        for (int kk = 0; kk < 2; kk++) {
            uint32_t afr[4][4];
            uint32_t bfr[4][2];
#pragma unroll
            for (int mi = 0; mi < 4; mi++) {
                uint32_t addr = s2u(&As[buf][(wm * 64 + mi * 16 + (lane & 15)) * APAD +
                                             kk * 16 + (lane >> 4) * 8]);
                ldsm_x4(afr[mi], addr);
            }
#pragma unroll
            for (int ni = 0; ni < 4; ni++) {
                uint32_t addr = s2u(&Bs[buf][(kk * 16 + (lane & 15)) * BPAD +
                                             wn * 32 + ni * 8]);
                ldsm_x2t(bfr[ni], addr);
            }
#pragma unroll
            for (int mi = 0; mi < 4; mi++)
#pragma unroll
                for (int ni = 0; ni < 4; ni++)
                    mma16816(acc[mi][ni], afr[mi], bfr[ni]);
        }

        if (kc + 1 < NK) {
            const int nbuf = buf ^ 1;
#pragma unroll
            for (int l = 0; l < 2; l++) *(uint4*)&As[nbuf][asoff[l]] = ra[l];
#pragma unroll
            for (int j = 0; j < 4; j++) {
                __half2 h01 = __floats2half2_rn(rb[j].x, rb[j].y);
                __half2 h23 = __floats2half2_rn(rb[j].z, rb[j].w);
                uint2 pk = make_uint2(*(uint32_t*)&h01, *(uint32_t*)&h23);
                *(uint2*)&Bs[nbuf][bsoff[j]] = pk;
            }
        }
        __syncthreads();
    }

    // ---- epilogue
#pragma unroll
    for (int mi = 0; mi < 4; mi++) {
#pragma unroll
        for (int ni = 0; ni < 4; ni++) {
            int r = wm * 64 + mi * 16 + (lane >> 2);
            int c = n0 + wn * 32 + ni * 8 + ((lane & 3) << 1);
            float bv0 = biasg[(size_t)e * NDIM + c];
            float bv1 = biasg[(size_t)e * NDIM + c + 1];
            float v00 = acc[mi][ni][0] + bv0, v01 = acc[mi][ni][1] + bv1;
            float v10 = acc[mi][ni][2] + bv0, v11 = acc[mi][ni][3] + bv1;
            if (MODE == 0) {
                v00 = fmaxf(v00, 0.f); v01 = fmaxf(v01, 0.f);
                v10 = fmaxf(v10, 0.f); v11 = fmaxf(v11, 0.f);
                __half2 p0 = __floats2half2_rn(v00, v01);
                __half2 p1 = __floats2half2_rn(v10, v11);
                if (m0 + r < cnt)
                    *(__half2*)&g_h[(size_t)(off + m0 + r) * HDIM + c] = p0;
                if (m0 + r + 8 < cnt)
                    *(__half2*)&g_h[(size_t)(off + m0 + r + 8) * HDIM + c] = p1;
            } else {
                if (m0 + r < cnt)
                    *(float2*)&g_y[(size_t)(off + m0 + r) * DDIM + c] = make_float2(v00, v01);
                if (m0 + r + 8 < cnt)
                    *(float2*)&g_y[(size_t)(off + m0 + r + 8) * DDIM + c] = make_float2(v10, v11);
            }
        }
    }
}

// ------------------------- kernel 5: combine ---------------------------------
// out[t,:] = g0 * y[row0,:] + g1 * y[row1,:]   (deterministic; no atomics)
__global__ void k_combine(float* __restrict__ out) {
    int t = blockIdx.x;
    int e0 = g_tok_e[t][0], e1 = g_tok_e[t][1];
    int r0 = g_off[e0] + g_tok_p[t][0];
    int r1 = g_off[e1] + g_tok_p[t][1];
    float w0 = g_tok_g[t][0], w1 = g_tok_g[t][1];

    const float4* ya = (const float4*)(g_y + (size_t)r0 * DDIM);
    const float4* yb = (const float4*)(g_y + (size_t)r1 * DDIM);
    float4* o = (float4*)(out + (size_t)t * DDIM);
    int i = threadIdx.x;  // 256 threads * float4 = 1024 floats
    float4 a = ya[i], b = yb[i];
    o[i] = make_float4(w0 * a.x + w1 * b.x,
                       w0 * a.y + w1 * b.y,
                       w0 * a.z + w1 * b.z,
                       w0 * a.w + w1 * b.w);
}

// ------------------------- launch --------------------------------------------
extern "C" void kernel_launch(void* const* d_in, const int* in_sizes, int n_in,
                              void* d_out, int out_size) {
    const float* x  = (const float*)d_in[0];
    const float* Wr = (const float*)d_in[1];
    const float* br = (const float*)d_in[2];
    const float* W1 = (const float*)d_in[3];
    const float* b1 = (const float*)d_in[4];
    const float* W2 = (const float*)d_in[5];
    const float* b2 = (const float*)d_in[6];
    float* out = (float*)d_out;

    k_init<<<1, 32>>>();
    k_router<<<TOKENS / 8, 256>>>(x, Wr, br);
    k_offsets<<<1, 1>>>();

    dim3 g1(HDIM / BN, TOKENS / BM, NEXP);  // (32, 64, 8); most m-tiles early-exit
    k_gemm<DDIM, HDIM, 0><<<g1, 256>>>(W1, b1);

    dim3 g2(DDIM / BN, TOKENS / BM, NEXP);  // (8, 64, 8)
    k_gemm<HDIM, DDIM, 1><<<g2, 256>>>(W2, b2);

    k_combine<<<TOKENS, 256>>>(out);
}

// round 3
// speedup vs baseline: 1.5389x; 1.5389x over previous
#include <cuda_runtime.h>
#include <cuda_fp16.h>
#include <cstdint>
#include <math.h>

// Problem constants
#define TOKENS 8192          // B*S
#define DDIM   1024
#define HDIM   4096
#define NEXP   8
#define TOTROWS (2*TOKENS)   // top-2 -> exactly 2*T expert-rows total

// ------------------------- device scratch (static, no allocs) ---------------
__device__ __half g_x16[(size_t)TOKENS * DDIM];                 // x in fp16
__device__ __half g_h[(size_t)(TOTROWS + 128) * HDIM];          // relu(xW1+b1), expert-sorted rows (+pad rows)
__device__ float  g_y[(size_t)TOTROWS * DDIM];                  // hW2+b2 per expert-row
__device__ int    g_cnt[NEXP];
__device__ int    g_off[NEXP];
__device__ int    g_idx[NEXP][TOKENS];                          // token id per expert slot
__device__ int    g_tok_e[TOKENS][2];
__device__ int    g_tok_p[TOKENS][2];
__device__ float  g_tok_g[TOKENS][2];

// ------------------------- small helpers ------------------------------------
__device__ __forceinline__ uint32_t s2u(const void* p) {
    return (uint32_t)__cvta_generic_to_shared(p);
}
__device__ __forceinline__ void ldsm_x4(uint32_t* r, uint32_t addr) {
    asm volatile("ldmatrix.sync.aligned.m8n8.x4.shared.b16 {%0,%1,%2,%3}, [%4];"
                 : "=r"(r[0]), "=r"(r[1]), "=r"(r[2]), "=r"(r[3]) : "r"(addr));
}
__device__ __forceinline__ void ldsm_x2t(uint32_t* r, uint32_t addr) {
    asm volatile("ldmatrix.sync.aligned.m8n8.x2.trans.shared.b16 {%0,%1}, [%2];"
                 : "=r"(r[0]), "=r"(r[1]) : "r"(addr));
}
__device__ __forceinline__ void mma16816(float* c, const uint32_t* a, const uint32_t* b) {
    asm volatile("mma.sync.aligned.m16n8k16.row.col.f32.f16.f16.f32 "
                 "{%0,%1,%2,%3}, {%4,%5,%6,%7}, {%8,%9}, {%0,%1,%2,%3};"
                 : "+f"(c[0]), "+f"(c[1]), "+f"(c[2]), "+f"(c[3])
                 : "r"(a[0]), "r"(a[1]), "r"(a[2]), "r"(a[3]), "r"(b[0]), "r"(b[1]));
}

// ------------------------- kernel 0: init -----------------------------------
__global__ void k_init() {
    if (threadIdx.x < NEXP) g_cnt[threadIdx.x] = 0;
}

// ------------------------- kernel 1: router ----------------------------------
// 1 warp per token: logits = x@Wr + br (fp32), softmax-top2 renormalized gates,
// atomic slot assignment per expert; also converts x row to fp16.
__global__ void k_router(const float* __restrict__ x,
                         const float* __restrict__ Wr,
                         const float* __restrict__ br) {
    int t    = blockIdx.x * 8 + (threadIdx.x >> 5);
    int lane = threadIdx.x & 31;
    if (t >= TOKENS) return;

    const float* xr = x + (size_t)t * DDIM;
    float acc[NEXP];
#pragma unroll
    for (int e = 0; e < NEXP; e++) acc[e] = 0.f;

    for (int j = 0; j < DDIM / 32; j++) {
        int d = j * 32 + lane;
        float xv = xr[d];
        g_x16[(size_t)t * DDIM + d] = __float2half_rn(xv);
        const float4* wr4 = (const float4*)(Wr + (size_t)d * NEXP);
        float4 w0 = wr4[0], w1 = wr4[1];
        acc[0] += xv * w0.x; acc[1] += xv * w0.y;
        acc[2] += xv * w0.z; acc[3] += xv * w0.w;
        acc[4] += xv * w1.x; acc[5] += xv * w1.y;
        acc[6] += xv * w1.z; acc[7] += xv * w1.w;
    }
#pragma unroll
    for (int o = 16; o; o >>= 1) {
#pragma unroll
        for (int e = 0; e < NEXP; e++)
            acc[e] += __shfl_xor_sync(0xffffffffu, acc[e], o);
    }

    if (lane == 0) {
#pragma unroll
        for (int e = 0; e < NEXP; e++) acc[e] += br[e];
        // top-1 (first max on tie, matching lax.top_k)
        int i0 = 0;
#pragma unroll
        for (int e = 1; e < NEXP; e++) if (acc[e] > acc[i0]) i0 = e;
        // top-2
        int i1 = -1;
#pragma unroll
        for (int e = 0; e < NEXP; e++) {
            if (e == i0) continue;
            if (i1 < 0 || acc[e] > acc[i1]) i1 = e;
        }
        // normalized top-2 softmax weights: full-softmax denominator cancels
        float ex = expf(acc[i1] - acc[i0]);
        float g0 = 1.f / (1.f + ex);
        float g1 = ex * g0;

        int p0 = atomicAdd(&g_cnt[i0], 1);
        int p1 = atomicAdd(&g_cnt[i1], 1);
        g_idx[i0][p0] = t;
        g_idx[i1][p1] = t;
        g_tok_e[t][0] = i0; g_tok_p[t][0] = p0; g_tok_g[t][0] = g0;
        g_tok_e[t][1] = i1; g_tok_p[t][1] = p1; g_tok_g[t][1] = g1;
    }
}

// ------------------------- kernel 2: offsets ---------------------------------
__global__ void k_offsets() {
    if (threadIdx.x == 0) {
        int s = 0;
        for (int e = 0; e < NEXP; e++) { g_off[e] = s; s += g_cnt[e]; }
    }
}

// ------------------------- kernel 3/4: grouped GEMM ---------------------------
// MODE 0: h[off+m, :] = relu( x16[gather(m), :KDIM] @ W1[e] + b1[e] )  (fp16 out)
// MODE 1: y[off+m, :] =        h[off+m, :KDIM]       @ W2[e] + b2[e]  (fp32 out)
// Tile 128x128x32, 256 threads, 8 warps as 2(m) x 4(n), warp tile 64x32.
#define BM 128
#define BN 128
#define BK 32
#define APAD 48    // halves per A-smem row (96B, 16B-aligned, reduces conflicts)
#define BPAD 136   // halves per B-smem row (272B, 16B-aligned)

template <int KDIM, int NDIM, int MODE>
__global__ __launch_bounds__(256) void k_gemm(const float* __restrict__ Wg,
                                              const float* __restrict__ biasg) {
    __shared__ __align__(16) __half As[2][BM * APAD];
    __shared__ __align__(16) __half Bs[2][BK * BPAD];

    const int e   = blockIdx.z;
    const int cnt = g_cnt[e];
    const int m0  = blockIdx.y * BM;
    if (m0 >= cnt) return;
    const int n0  = blockIdx.x * BN;
    const int off = g_off[e];
    const float* Wb = Wg + (size_t)e * KDIM * NDIM;

    const int tid  = threadIdx.x;
    const int lane = tid & 31;
    const int warp = tid >> 5;
    const int wm   = warp >> 2;   // 0..1
    const int wn   = warp & 3;    // 0..3

    // ---- A-load mapping: 2 x uint4 (8 halves) per thread, 128 rows x 4 segs
    const __half* aptr[2];
    int asoff[2];
#pragma unroll
    for (int l = 0; l < 2; l++) {
        int flat = tid + 256 * l;
        int row  = flat >> 2;       // 0..127
        int seg  = flat & 3;        // 0..3 (8-half segments)
        const __half* base;
        if (MODE == 0) {
            int tok = (m0 + row < cnt) ? g_idx[e][m0 + row] : 0;
            base = g_x16 + (size_t)tok * DDIM;
        } else {
            int rg = off + m0 + row;          // < TOTROWS+128 (padded)
            base = g_h + (size_t)rg * HDIM;
        }
        aptr[l]  = base + seg * 8;
        asoff[l] = row * APAD + seg * 8;
    }

    // ---- B-load mapping: 4 x float4 per thread, 32 rows x 32 float4-cols
    const float* bptr[4];
    int bsoff[4];
#pragma unroll
    for (int j = 0; j < 4; j++) {
        int idx = tid + 256 * j;    // 0..1023
        int row = idx >> 5;         // 0..31
        int col = (idx & 31) * 4;   // 0..124
        bptr[j]  = Wb + (size_t)row * NDIM + n0 + col;
        bsoff[j] = row * BPAD + col;
    }

    float acc[4][4][4];
#pragma unroll
    for (int mi = 0; mi < 4; mi++)
#pragma unroll
        for (int ni = 0; ni < 4; ni++)
#pragma unroll
            for (int q = 0; q < 4; q++) acc[mi][ni][q] = 0.f;

    uint4  ra[2];
    float4 rb[4];

    // prologue: chunk 0 -> smem[0]
#pragma unroll
    for (int l = 0; l < 2; l++) ra[l] = *(const uint4*)(aptr[l]);
#pragma unroll
    for (int j = 0; j < 4; j++) rb[j] = *(const float4*)(bptr[j]);
#pragma unroll
    for (int l = 0; l < 2; l++) *(uint4*)&As[0][asoff[l]] = ra[l];
#pragma unroll
    for (int j = 0; j < 4; j++) {
        __half2 h01 = __floats2half2_rn(rb[j].x, rb[j].y);
        __half2 h23 = __floats2half2_rn(rb[j].z, rb[j].w);
        uint2 pk = make_uint2(*(uint32_t*)&h01, *(uint32_t*)&h23);
        *(uint2*)&Bs[0][bsoff[j]] = pk;
    }
    __syncthreads();

    const int NK = KDIM / BK;
    for (int kc = 0; kc < NK; kc++) {
        const int buf = kc & 1;
        if (kc + 1 < NK) {
            int k0 = (kc + 1) * BK;
#pragma unroll
            for (int l = 0; l < 2; l++) ra[l] = *(const uint4*)(aptr[l] + k0);
#pragma unroll
            for (int j = 0; j < 4; j++) rb[j] = *(const float4*)(bptr[j] + (size_t)k0 * NDIM);
        }

        // compute from smem[buf]
#pragma unroll
        for (int kk = 0; kk < 2; kk++) {
            uint32_t afr[4][4];
            uint32_t bfr[4][2];
#pragma unroll
            for (int mi = 0; mi < 4; mi++) {
                uint32_t addr = s2u(&As[buf][(wm * 64 + mi * 16 + (lane & 15)) * APAD +
                                             kk * 16 + (lane >> 4) * 8]);
                ldsm_x4(afr[mi], addr);
            }
#pragma unroll
            for (int ni = 0; ni < 4; ni++) {
                uint32_t addr = s2u(&Bs[buf][(kk * 16 + (lane & 15)) * BPAD +
                                             wn * 32 + ni * 8]);
                ldsm_x2t(bfr[ni], addr);
            }
#pragma unroll
            for (int mi = 0; mi < 4; mi++)
#pragma unroll
                for (int ni = 0; ni < 4; ni++)
                    mma16816(acc[mi][ni], afr[mi], bfr[ni]);
        }

        if (kc + 1 < NK) {
            const int nbuf = buf ^ 1;
#pragma unroll
            for (int l = 0; l < 2; l++) *(uint4*)&As[nbuf][asoff[l]] = ra[l];
#pragma unroll
            for (int j = 0; j < 4; j++) {
                __half2 h01 = __floats2half2_rn(rb[j].x, rb[j].y);
                __half2 h23 = __floats2half2_rn(rb[j].z, rb[j].w);
                uint2 pk = make_uint2(*(uint32_t*)&h01, *(uint32_t*)&h23);
                *(uint2*)&Bs[nbuf][bsoff[j]] = pk;
            }
        }
        __syncthreads();
    }

    // ---- epilogue
#pragma unroll
    for (int mi = 0; mi < 4; mi++) {
#pragma unroll
        for (int ni = 0; ni < 4; ni++) {
            int r = wm * 64 + mi * 16 + (lane >> 2);
            int c = n0 + wn * 32 + ni * 8 + ((lane & 3) << 1);
            float bv0 = biasg[(size_t)e * NDIM + c];
            float bv1 = biasg[(size_t)e * NDIM + c + 1];
            float v00 = acc[mi][ni][0] + bv0, v01 = acc[mi][ni][1] + bv1;
            float v10 = acc[mi][ni][2] + bv0, v11 = acc[mi][ni][3] + bv1;
            if (MODE == 0) {
                v00 = fmaxf(v00, 0.f); v01 = fmaxf(v01, 0.f);
                v10 = fmaxf(v10, 0.f); v11 = fmaxf(v11, 0.f);
                __half2 p0 = __floats2half2_rn(v00, v01);
                __half2 p1 = __floats2half2_rn(v10, v11);
                if (m0 + r < cnt)
                    *(__half2*)&g_h[(size_t)(off + m0 + r) * HDIM + c] = p0;
                if (m0 + r + 8 < cnt)
                    *(__half2*)&g_h[(size_t)(off + m0 + r + 8) * HDIM + c] = p1;
            } else {
                if (m0 + r < cnt)
                    *(float2*)&g_y[(size_t)(off + m0 + r) * DDIM + c] = make_float2(v00, v01);
                if (m0 + r + 8 < cnt)
                    *(float2*)&g_y[(size_t)(off + m0 + r + 8) * DDIM + c] = make_float2(v10, v11);
            }
        }
    }
}

// ------------------------- kernel 5: combine ---------------------------------
// out[t,:] = g0 * y[row0,:] + g1 * y[row1,:]   (deterministic; no atomics)
__global__ void k_combine(float* __restrict__ out) {
    int t = blockIdx.x;
    int e0 = g_tok_e[t][0], e1 = g_tok_e[t][1];
    int r0 = g_off[e0] + g_tok_p[t][0];
    int r1 = g_off[e1] + g_tok_p[t][1];
    float w0 = g_tok_g[t][0], w1 = g_tok_g[t][1];

    const float4* ya = (const float4*)(g_y + (size_t)r0 * DDIM);
    const float4* yb = (const float4*)(g_y + (size_t)r1 * DDIM);
    float4* o = (float4*)(out + (size_t)t * DDIM);
    int i = threadIdx.x;  // 256 threads * float4 = 1024 floats
    float4 a = ya[i], b = yb[i];
    o[i] = make_float4(w0 * a.x + w1 * b.x,
                       w0 * a.y + w1 * b.y,
                       w0 * a.z + w1 * b.z,
                       w0 * a.w + w1 * b.w);
}

// ------------------------- launch --------------------------------------------
extern "C" void kernel_launch(void* const* d_in, const int* in_sizes, int n_in,
                              void* d_out, int out_size) {
    const float* x  = (const float*)d_in[0];
    const float* Wr = (const float*)d_in[1];
    const float* br = (const float*)d_in[2];
    const float* W1 = (const float*)d_in[3];
    const float* b1 = (const float*)d_in[4];
    const float* W2 = (const float*)d_in[5];
    const float* b2 = (const float*)d_in[6];
    float* out = (float*)d_out;

    k_init<<<1, 32>>>();
    k_router<<<TOKENS / 8, 256>>>(x, Wr, br);
    k_offsets<<<1, 1>>>();

    dim3 g1(HDIM / BN, TOKENS / BM, NEXP);  // (32, 64, 8); most m-tiles early-exit
    k_gemm<DDIM, HDIM, 0><<<g1, 256>>>(W1, b1);

    dim3 g2(DDIM / BN, TOKENS / BM, NEXP);  // (8, 64, 8)
    k_gemm<HDIM, DDIM, 1><<<g2, 256>>>(W2, b2);

    k_combine<<<TOKENS, 256>>>(out);
}